// round 3
// baseline (speedup 1.0000x reference)
#include <cuda_runtime.h>
#include <cuda_fp16.h>

#define D        64
#define N_MAX    100000
#define E_MAX    800000
#define NC_NODES 500
#define EC_MAX   20000
#define HP       6
#define SCAN_BLK 1024
#define NBLK_MAX ((N_MAX + SCAN_BLK - 1) / SCAN_BLK)

// Static scratch
__device__ __half g_nhalf[N_MAX * D];   // fp16 copy of nfeat (pass1 only)
__device__ float  g_wslot[E_MAX];       // softmax weight, stored per CSR slot
__device__ float  g_cw[EC_MAX];
__device__ float  g_cdenom[NC_NODES];
__device__ float  g_trel[HP * D];
__device__ int    g_cnt[N_MAX];
__device__ int    g_off[N_MAX];         // within-block exclusive prefix
__device__ int    g_bsum[NBLK_MAX];
__device__ int    g_bpre[NBLK_MAX];
__device__ int    g_start[N_MAX + 1];   // CSR row pointers
__device__ int    g_cursor[N_MAX];
__device__ int    g_slot_src[E_MAX];    // CSR slot -> src node
__device__ int    g_eslot[E_MAX];       // edge -> CSR slot

// ---------------------------------------------------------------------------
__device__ __forceinline__ float warp_sum(float v) {
    #pragma unroll
    for (int o = 16; o > 0; o >>= 1) v += __shfl_xor_sync(0xffffffffu, v, o);
    return v;
}
__device__ __forceinline__ float half_sum(float v) {
    #pragma unroll
    for (int o = 8; o > 0; o >>= 1) v += __shfl_xor_sync(0xffffffffu, v, o);
    return v;
}
__device__ __forceinline__ void red_add_v4(float* p, float x, float y, float z, float w) {
    asm volatile("red.global.add.v4.f32 [%0], {%1,%2,%3,%4};"
                 :: "l"(p), "f"(x), "f"(y), "f"(z), "f"(w) : "memory");
}

// ---------------------------------------------------------------------------
// K0: fp16 convert, zero counters/cat_hid/cat denom, compute time_rel (blocks 0..5)
__global__ void k0_init(const float* __restrict__ nfeat, int NN,
                        float* __restrict__ cat_hid,
                        const float* __restrict__ hour_emb,
                        const float* __restrict__ W,
                        const float* __restrict__ b) {
    int stride = gridDim.x * blockDim.x;
    int tid = blockIdx.x * blockDim.x + threadIdx.x;

    const float2* nf2 = (const float2*)nfeat;
    __half2* nh2 = (__half2*)g_nhalf;
    int n2 = NN * D / 2;
    for (int i = tid; i < n2; i += stride)
        nh2[i] = __float22half2_rn(nf2[i]);
    for (int i = tid; i < NN; i += stride)
        g_cnt[i] = 0;
    for (int i = tid; i < NC_NODES * D; i += stride)
        cat_hid[i] = 0.f;
    for (int i = tid; i < NC_NODES; i += stride)
        g_cdenom[i] = 0.f;

    if (blockIdx.x < HP) {
        __shared__ float mix[D];
        __shared__ float red[D];
        int h = blockIdx.x;
        int j = threadIdx.x;
        if (j < D) {
            int lh = (h - 1 + HP) % HP, nh = (h + 1) % HP;
            mix[j] = (hour_emb[lh * D + j] + hour_emb[h * D + j] + hour_emb[nh * D + j]) * (1.f / 3.f);
        }
        __syncthreads();
        float o = 0.f;
        if (j < D) {
            o = b[j];
            #pragma unroll
            for (int k = 0; k < D; k++) o = fmaf(W[j * D + k], mix[k], o);
            red[j] = o * o;
        }
        __syncthreads();
        #pragma unroll
        for (int s = 32; s > 0; s >>= 1) {
            if (j < s) red[j] += red[j + s];
            __syncthreads();
        }
        if (j < D) g_trel[h * D + j] = o / fmaxf(sqrtf(red[0]), 1e-12f);
    }
}

// K1: histogram of dst
__global__ void k1_count(const int* __restrict__ dst, int E) {
    int stride = gridDim.x * blockDim.x;
    for (int e = blockIdx.x * blockDim.x + threadIdx.x; e < E; e += stride)
        atomicAdd(&g_cnt[dst[e]], 1);
}

// K2: per-block scan (1024 elements/block, 256 threads x 4)
__global__ void k2_scan_blocks(int NN) {
    __shared__ int sh[256];
    int b = blockIdx.x, t = threadIdx.x;
    int base = b * SCAN_BLK + t * 4;
    int v0 = (base + 0 < NN) ? g_cnt[base + 0] : 0;
    int v1 = (base + 1 < NN) ? g_cnt[base + 1] : 0;
    int v2 = (base + 2 < NN) ? g_cnt[base + 2] : 0;
    int v3 = (base + 3 < NN) ? g_cnt[base + 3] : 0;
    int s = v0 + v1 + v2 + v3;
    sh[t] = s;
    __syncthreads();
    #pragma unroll
    for (int off = 1; off < 256; off <<= 1) {
        int x = (t >= off) ? sh[t - off] : 0;
        __syncthreads();
        sh[t] += x;
        __syncthreads();
    }
    if (t == 255) g_bsum[b] = sh[255];
    int run = sh[t] - s;
    if (base + 0 < NN) g_off[base + 0] = run; run += v0;
    if (base + 1 < NN) g_off[base + 1] = run; run += v1;
    if (base + 2 < NN) g_off[base + 2] = run; run += v2;
    if (base + 3 < NN) g_off[base + 3] = run;
}

// K3: scan the (<=98) block sums serially
__global__ void k3_scan_sums(int nblk) {
    if (threadIdx.x == 0 && blockIdx.x == 0) {
        int run = 0;
        for (int i = 0; i < nblk; i++) {
            int t = g_bsum[i];
            g_bpre[i] = run;
            run += t;
        }
    }
}

// K4: finalize row pointers + cursors
__global__ void k4_finalize(int NN, int E) {
    int stride = gridDim.x * blockDim.x;
    int tid = blockIdx.x * blockDim.x + threadIdx.x;
    for (int i = tid; i < NN; i += stride) {
        int v = g_off[i] + g_bpre[i >> 10];
        g_start[i] = v;
        g_cursor[i] = v;
    }
    if (tid == 0) g_start[NN] = E;
}

// K5: scatter edges into CSR slots
__global__ void k5_scatter(const int* __restrict__ src,
                           const int* __restrict__ dst, int E) {
    int stride = gridDim.x * blockDim.x;
    for (int e = blockIdx.x * blockDim.x + threadIdx.x; e < E; e += stride) {
        int d = dst[e];
        int pos = atomicAdd(&g_cursor[d], 1);
        g_slot_src[pos] = src[e];
        g_eslot[e] = pos;
    }
}

// ---------------------------------------------------------------------------
// K6: pass-1 scores. warps < EC: cat edges (fp32). Others: 2 main edges/warp (fp16 rows).
__global__ void k6_pass1(const float* __restrict__ cat_emb,
                         const float* __restrict__ rel_emb,
                         const float* __restrict__ norm_emb,
                         const int* __restrict__ src,
                         const int* __restrict__ dst,
                         const int* __restrict__ ftype,
                         const int* __restrict__ hourid,
                         const int* __restrict__ csrc,
                         const int* __restrict__ cdst,
                         int E, int EC, int n_warps) {
    int w = (blockIdx.x * blockDim.x + threadIdx.x) >> 5;
    int lane = threadIdx.x & 31;
    if (w >= n_warps) return;

    if (w < EC) {
        int e = w;
        int s = csrc[e], d = cdst[e];
        const float2* ce2 = (const float2*)cat_emb;
        const float2* re2 = (const float2*)rel_emb;
        float2 hc = ce2[s * 32 + lane];
        float2 tc = ce2[d * 32 + lane];
        float2 rc = re2[6 * 32 + lane];
        float dx = hc.x + rc.x - tc.x;
        float dy = hc.y + rc.y - tc.y;
        float ssq = warp_sum(fmaf(dx, dx, dy * dy));
        if (lane == 0) {
            float wgt = __expf(__expf(-ssq));
            g_cw[e] = wgt;
            atomicAdd(&g_cdenom[d], wgt);
        }
    } else {
        int p = w - EC;
        int half = lane >> 4;
        int l = lane & 15;
        int e = 2 * p + half;
        if (e >= E) return;
        int s = src[e], d = dst[e], f = ftype[e], h = hourid[e];

        const float2* nh2 = (const float2*)g_nhalf;     // 4 halfs per float2
        float2 ra = nh2[s * 16 + l];
        float2 rb = nh2[d * 16 + l];
        __half2* pa = (__half2*)&ra;
        __half2* pb = (__half2*)&rb;
        float2 a0 = __half22float2(pa[0]), a1 = __half22float2(pa[1]);
        float2 b0 = __half22float2(pb[0]), b1 = __half22float2(pb[1]);
        float ux = a0.x - b0.x, uy = a0.y - b0.y, uz = a1.x - b1.x, uw = a1.y - b1.y;

        const float4* nm4 = (const float4*)norm_emb;
        const float4* re4 = (const float4*)rel_emb;
        const float4* tr4 = (const float4*)g_trel;
        float4 n  = nm4[f * 16 + l];
        float4 tn = nm4[5 * 16 + l];

        float dot1 = half_sum(fmaf(ux, n.x,  fmaf(uy, n.y,  fmaf(uz, n.z,  uw * n.w))));
        float dot2 = half_sum(fmaf(ux, tn.x, fmaf(uy, tn.y, fmaf(uz, tn.z, uw * tn.w))));

        float4 r  = re4[f * 16 + l];
        float4 tr = tr4[h * 16 + l];

        float e1x = ux - dot1 * n.x + r.x;
        float e1y = uy - dot1 * n.y + r.y;
        float e1z = uz - dot1 * n.z + r.z;
        float e1w = uw - dot1 * n.w + r.w;
        float e2x = ux - dot2 * tn.x + tr.x;
        float e2y = uy - dot2 * tn.y + tr.y;
        float e2z = uz - dot2 * tn.z + tr.z;
        float e2w = uw - dot2 * tn.w + tr.w;

        float ssq = half_sum(
            fmaf(e1x, e1x, fmaf(e1y, e1y, fmaf(e1z, e1z, e1w * e1w))) +
            fmaf(e2x, e2x, fmaf(e2y, e2y, fmaf(e2z, e2z, e2w * e2w))));

        if (l == 0) {
            float wgt = __expf(__expf(-ssq));
            g_wslot[g_eslot[e]] = wgt;   // store per CSR slot; no denom atomic
        }
    }
}

// ---------------------------------------------------------------------------
// K7: aggregation. warps < ECH: cat pass2 (REDG). Others: 2 nodes/warp CSR gather.
__global__ void k7_aggregate(const float* __restrict__ nfeat,
                             const float* __restrict__ cat_emb,
                             const int* __restrict__ csrc,
                             const int* __restrict__ cdst,
                             float* __restrict__ rst,
                             float* __restrict__ cat_hid,
                             int NN, int EC, int ECH, int n_warps) {
    int w = (blockIdx.x * blockDim.x + threadIdx.x) >> 5;
    int lane = threadIdx.x & 31;
    if (w >= n_warps) return;
    int half = lane >> 4;
    int l = lane & 15;

    if (w < ECH) {
        int e = 2 * w + half;
        if (e >= EC) return;
        int s = csrc[e], d = cdst[e];
        float coeff = g_cw[e] / g_cdenom[d];
        float4 v = ((const float4*)cat_emb)[s * 16 + l];
        red_add_v4(&cat_hid[d * D + l * 4],
                   v.x * coeff, v.y * coeff, v.z * coeff, v.w * coeff);
    } else {
        int node = 2 * (w - ECH) + half;
        if (node >= NN) return;
        int st = g_start[node], en = g_start[node + 1];
        float4 acc = make_float4(0.f, 0.f, 0.f, 0.f);
        if (en > st) {
            float denom = 0.f;
            for (int j = st + l; j < en; j += 16) denom += g_wslot[j];
            denom = half_sum(denom);
            float inv = 1.f / denom;
            const float4* nf4 = (const float4*)nfeat;
            for (int j = st; j < en; j++) {
                float cw = g_wslot[j] * inv;   // broadcast
                int s = g_slot_src[j];          // broadcast
                float4 v = nf4[s * 16 + l];
                acc.x = fmaf(cw, v.x, acc.x);
                acc.y = fmaf(cw, v.y, acc.y);
                acc.z = fmaf(cw, v.z, acc.z);
                acc.w = fmaf(cw, v.w, acc.w);
            }
        }
        ((float4*)rst)[node * 16 + l] = acc;
    }
}

// ---------------------------------------------------------------------------
extern "C" void kernel_launch(void* const* d_in, const int* in_sizes, int n_in,
                              void* d_out, int out_size) {
    const float* nfeat      = (const float*)d_in[0];
    const float* cat_emb    = (const float*)d_in[1];
    const float* rel_emb    = (const float*)d_in[2];
    const float* norm_emb   = (const float*)d_in[3];
    const float* hour_emb   = (const float*)d_in[4];
    const float* time_rel_w = (const float*)d_in[5];
    const float* time_rel_b = (const float*)d_in[6];
    const int*   src        = (const int*)d_in[7];
    const int*   dst        = (const int*)d_in[8];
    const int*   ftype      = (const int*)d_in[9];
    const int*   hourid     = (const int*)d_in[10];
    const int*   cat_src    = (const int*)d_in[11];
    const int*   cat_dst    = (const int*)d_in[12];

    const int NN = in_sizes[0] / D;
    const int E  = in_sizes[7];
    const int EC = in_sizes[11];

    float* out     = (float*)d_out;
    float* rst     = out;
    float* cat_hid = out + NN * D;

    // K0: convert + zeros + time_rel
    k0_init<<<1024, 256>>>(nfeat, NN, cat_hid, hour_emb, time_rel_w, time_rel_b);

    // CSR build
    k1_count<<<1024, 256>>>(dst, E);
    int nblk = (NN + SCAN_BLK - 1) / SCAN_BLK;
    k2_scan_blocks<<<nblk, 256>>>(NN);
    k3_scan_sums<<<1, 32>>>(nblk);
    k4_finalize<<<256, 256>>>(NN, E);
    k5_scatter<<<1024, 256>>>(src, dst, E);

    // Pass 1 (scores)
    {
        int n_warps = EC + (E + 1) / 2;
        int blocks = (n_warps * 32 + 255) / 256;
        k6_pass1<<<blocks, 256>>>(cat_emb, rel_emb, norm_emb,
                                  src, dst, ftype, hourid, cat_src, cat_dst,
                                  E, EC, n_warps);
    }

    // Pass 2 (aggregate)
    {
        int ECH = (EC + 1) / 2;
        int n_warps = ECH + (NN + 1) / 2;
        int blocks = (n_warps * 32 + 255) / 256;
        k7_aggregate<<<blocks, 256>>>(nfeat, cat_emb, cat_src, cat_dst,
                                      rst, cat_hid, NN, EC, ECH, n_warps);
    }
}

// round 4
// speedup vs baseline: 1.0747x; 1.0747x over previous
#include <cuda_runtime.h>
#include <cuda_fp16.h>

#define D        64
#define N_MAX    100000
#define NC_NODES 500
#define HP       6

// Static scratch
__device__ __half g_nhalf[N_MAX * D];   // fp16 copy of nfeat
__device__ float  g_w[800000];          // softmax weight per main edge
__device__ float  g_cw[20000];          // per cat edge
__device__ float  g_denom[N_MAX];
__device__ float  g_cdenom[NC_NODES];
__device__ float  g_trel[HP * D];

// ---------------------------------------------------------------------------
__device__ __forceinline__ float warp_sum(float v) {
    #pragma unroll
    for (int o = 16; o > 0; o >>= 1) v += __shfl_xor_sync(0xffffffffu, v, o);
    return v;
}
__device__ __forceinline__ float half_sum(float v) {
    #pragma unroll
    for (int o = 8; o > 0; o >>= 1) v += __shfl_xor_sync(0xffffffffu, v, o);
    return v;
}
__device__ __forceinline__ void red_add_v4(float* p, float x, float y, float z, float w) {
    asm volatile("red.global.add.v4.f32 [%0], {%1,%2,%3,%4};"
                 :: "l"(p), "f"(x), "f"(y), "f"(z), "f"(w) : "memory");
}

// ---------------------------------------------------------------------------
// Init: fp16 convert of nfeat, zero denominators, time_rel precompute (blocks 0..5)
__global__ void init_kernel(const float* __restrict__ nfeat, int NN,
                            const float* __restrict__ hour_emb,
                            const float* __restrict__ W,
                            const float* __restrict__ b) {
    int stride = gridDim.x * blockDim.x;
    int tid = blockIdx.x * blockDim.x + threadIdx.x;

    const float2* nf2 = (const float2*)nfeat;
    __half2* nh2 = (__half2*)g_nhalf;
    int n2 = NN * D / 2;
    for (int i = tid; i < n2; i += stride)
        nh2[i] = __float22half2_rn(nf2[i]);
    for (int i = tid; i < NN; i += stride)
        g_denom[i] = 0.f;
    for (int i = tid; i < NC_NODES; i += stride)
        g_cdenom[i] = 0.f;

    if (blockIdx.x < HP) {
        __shared__ float mix[D];
        __shared__ float red[D];
        int h = blockIdx.x;
        int j = threadIdx.x;
        if (j < D) {
            int lh = (h - 1 + HP) % HP, nh = (h + 1) % HP;
            mix[j] = (hour_emb[lh * D + j] + hour_emb[h * D + j] + hour_emb[nh * D + j]) * (1.f / 3.f);
        }
        __syncthreads();
        float o = 0.f;
        if (j < D) {
            o = b[j];
            #pragma unroll
            for (int k = 0; k < D; k++) o = fmaf(W[j * D + k], mix[k], o);
            red[j] = o * o;
        }
        __syncthreads();
        #pragma unroll
        for (int s = 32; s > 0; s >>= 1) {
            if (j < s) red[j] += red[j + s];
            __syncthreads();
        }
        if (j < D) g_trel[h * D + j] = o / fmaxf(sqrtf(red[0]), 1e-12f);
    }
}

// ---------------------------------------------------------------------------
// Pass 1: scores + softmax denominators.
//   warp w < EC : category edge (fp32, full warp)
//   warp w >= EC: main edge pair, 16 lanes each, fp16 rows
__global__ void pass1_kernel(const float* __restrict__ cat_emb,
                             const float* __restrict__ rel_emb,
                             const float* __restrict__ norm_emb,
                             const int* __restrict__ src,
                             const int* __restrict__ dst,
                             const int* __restrict__ ftype,
                             const int* __restrict__ hourid,
                             const int* __restrict__ csrc,
                             const int* __restrict__ cdst,
                             int E, int EC, int n_warps) {
    int w = (blockIdx.x * blockDim.x + threadIdx.x) >> 5;
    int lane = threadIdx.x & 31;
    if (w >= n_warps) return;

    if (w < EC) {
        int e = w;
        int s = csrc[e], d = cdst[e];
        const float2* ce2 = (const float2*)cat_emb;
        const float2* re2 = (const float2*)rel_emb;
        float2 hc = ce2[s * 32 + lane];
        float2 tc = ce2[d * 32 + lane];
        float2 rc = re2[6 * 32 + lane];
        float dx = hc.x + rc.x - tc.x;
        float dy = hc.y + rc.y - tc.y;
        float ssq = warp_sum(fmaf(dx, dx, dy * dy));
        if (lane == 0) {
            float wgt = __expf(__expf(-ssq));
            g_cw[e] = wgt;
            atomicAdd(&g_cdenom[d], wgt);
        }
    } else {
        int p = w - EC;
        int half = lane >> 4;
        int l = lane & 15;
        int e = 2 * p + half;
        if (e >= E) return;
        int s = src[e], d = dst[e], f = ftype[e], h = hourid[e];

        const float2* nh2 = (const float2*)g_nhalf;   // 4 halfs per float2
        float2 ra = nh2[s * 16 + l];
        float2 rb = nh2[d * 16 + l];
        __half2* pa = (__half2*)&ra;
        __half2* pb = (__half2*)&rb;
        float2 a0 = __half22float2(pa[0]), a1 = __half22float2(pa[1]);
        float2 b0 = __half22float2(pb[0]), b1 = __half22float2(pb[1]);
        float ux = a0.x - b0.x, uy = a0.y - b0.y, uz = a1.x - b1.x, uw = a1.y - b1.y;

        const float4* nm4 = (const float4*)norm_emb;
        const float4* re4 = (const float4*)rel_emb;
        const float4* tr4 = (const float4*)g_trel;
        float4 n  = nm4[f * 16 + l];
        float4 tn = nm4[5 * 16 + l];

        float dot1 = half_sum(fmaf(ux, n.x,  fmaf(uy, n.y,  fmaf(uz, n.z,  uw * n.w))));
        float dot2 = half_sum(fmaf(ux, tn.x, fmaf(uy, tn.y, fmaf(uz, tn.z, uw * tn.w))));

        float4 r  = re4[f * 16 + l];
        float4 tr = tr4[h * 16 + l];

        float e1x = ux - dot1 * n.x + r.x;
        float e1y = uy - dot1 * n.y + r.y;
        float e1z = uz - dot1 * n.z + r.z;
        float e1w = uw - dot1 * n.w + r.w;
        float e2x = ux - dot2 * tn.x + tr.x;
        float e2y = uy - dot2 * tn.y + tr.y;
        float e2z = uz - dot2 * tn.z + tr.z;
        float e2w = uw - dot2 * tn.w + tr.w;

        float ssq = half_sum(
            fmaf(e1x, e1x, fmaf(e1y, e1y, fmaf(e1z, e1z, e1w * e1w))) +
            fmaf(e2x, e2x, fmaf(e2y, e2y, fmaf(e2z, e2z, e2w * e2w))));

        if (l == 0) {
            float wgt = __expf(__expf(-ssq));
            g_w[e] = wgt;
            atomicAdd(&g_denom[d], wgt);
        }
    }
}

// ---------------------------------------------------------------------------
// Pass 2: vectorized scatter-aggregate.
//   warp w < ECH : category edge pair (fp32 rows)
//   warp w >= ECH: main edge pair (fp16 rows)
__global__ void pass2_kernel(const float* __restrict__ cat_emb,
                             const int* __restrict__ src,
                             const int* __restrict__ dst,
                             const int* __restrict__ csrc,
                             const int* __restrict__ cdst,
                             float* __restrict__ rst,
                             float* __restrict__ cat_hid,
                             int E, int EC, int ECH, int n_warps) {
    int w = (blockIdx.x * blockDim.x + threadIdx.x) >> 5;
    int lane = threadIdx.x & 31;
    if (w >= n_warps) return;
    int half = lane >> 4;
    int l = lane & 15;

    if (w < ECH) {
        int e = 2 * w + half;
        if (e >= EC) return;
        int s = csrc[e], d = cdst[e];
        float coeff = g_cw[e] / g_cdenom[d];
        float4 v = ((const float4*)cat_emb)[s * 16 + l];
        red_add_v4(&cat_hid[d * D + l * 4],
                   v.x * coeff, v.y * coeff, v.z * coeff, v.w * coeff);
    } else {
        int e = 2 * (w - ECH) + half;
        if (e >= E) return;
        int s = src[e], d = dst[e];
        float coeff = g_w[e] / g_denom[d];
        const float2* nh2 = (const float2*)g_nhalf;
        float2 rv = nh2[s * 16 + l];
        __half2* pv = (__half2*)&rv;
        float2 v0 = __half22float2(pv[0]), v1 = __half22float2(pv[1]);
        red_add_v4(&rst[d * D + l * 4],
                   v0.x * coeff, v0.y * coeff, v1.x * coeff, v1.y * coeff);
    }
}

// ---------------------------------------------------------------------------
extern "C" void kernel_launch(void* const* d_in, const int* in_sizes, int n_in,
                              void* d_out, int out_size) {
    const float* nfeat      = (const float*)d_in[0];
    const float* cat_emb    = (const float*)d_in[1];
    const float* rel_emb    = (const float*)d_in[2];
    const float* norm_emb   = (const float*)d_in[3];
    const float* hour_emb   = (const float*)d_in[4];
    const float* time_rel_w = (const float*)d_in[5];
    const float* time_rel_b = (const float*)d_in[6];
    const int*   src        = (const int*)d_in[7];
    const int*   dst        = (const int*)d_in[8];
    const int*   ftype      = (const int*)d_in[9];
    const int*   hourid     = (const int*)d_in[10];
    const int*   cat_src    = (const int*)d_in[11];
    const int*   cat_dst    = (const int*)d_in[12];

    const int NN = in_sizes[0] / D;
    const int E  = in_sizes[7];
    const int EC = in_sizes[11];

    float* out     = (float*)d_out;
    float* rst     = out;
    float* cat_hid = out + NN * D;

    // Zero the output (REDG accumulates into it)
    cudaMemsetAsync(d_out, 0, (size_t)out_size * sizeof(float), 0);

    // Init: fp16 convert + denominators + time_rel
    init_kernel<<<2048, 256>>>(nfeat, NN, hour_emb, time_rel_w, time_rel_b);

    // Pass 1
    {
        int n_warps = EC + (E + 1) / 2;
        int blocks = (n_warps * 32 + 255) / 256;
        pass1_kernel<<<blocks, 256>>>(cat_emb, rel_emb, norm_emb,
                                      src, dst, ftype, hourid, cat_src, cat_dst,
                                      E, EC, n_warps);
    }

    // Pass 2
    {
        int ECH = (EC + 1) / 2;
        int n_warps = ECH + (E + 1) / 2;
        int blocks = (n_warps * 32 + 255) / 256;
        pass2_kernel<<<blocks, 256>>>(cat_emb, src, dst, cat_src, cat_dst,
                                      rst, cat_hid, E, EC, ECH, n_warps);
    }
}

// round 5
// speedup vs baseline: 1.0922x; 1.0163x over previous
#include <cuda_runtime.h>
#include <cuda_fp16.h>

#define D        64
#define N_MAX    100000
#define E_MAX    800000
#define NC_NODES 500
#define EC_MAX   20000
#define HP       6
#define SCAN_BLK 1024
#define NBLK_MAX ((N_MAX + SCAN_BLK - 1) / SCAN_BLK)

// Static scratch
__device__ __half g_nhalf[N_MAX * D];   // fp16 copy of nfeat
__device__ float  g_wslot[E_MAX];       // softmax weight per CSR slot
__device__ float  g_cw[EC_MAX];
__device__ float  g_cdenom[NC_NODES];
__device__ float  g_trel[HP * D];
__device__ int    g_cnt[N_MAX];         // zeroed via memset node each replay
__device__ int    g_off[N_MAX];
__device__ int    g_bsum[NBLK_MAX];
__device__ int    g_bpre[NBLK_MAX];
__device__ int    g_start[N_MAX + 1];
__device__ int    g_cursor[N_MAX];
__device__ int    g_slot_src[E_MAX];
__device__ int    g_eslot[E_MAX];

// ---------------------------------------------------------------------------
__device__ __forceinline__ float warp_sum(float v) {
    #pragma unroll
    for (int o = 16; o > 0; o >>= 1) v += __shfl_xor_sync(0xffffffffu, v, o);
    return v;
}
__device__ __forceinline__ float half_sum(float v) {
    #pragma unroll
    for (int o = 8; o > 0; o >>= 1) v += __shfl_xor_sync(0xffffffffu, v, o);
    return v;
}
__device__ __forceinline__ void red_add_v4(float* p, float x, float y, float z, float w) {
    asm volatile("red.global.add.v4.f32 [%0], {%1,%2,%3,%4};"
                 :: "l"(p), "f"(x), "f"(y), "f"(z), "f"(w) : "memory");
}

// ---------------------------------------------------------------------------
// K0: fp16 convert + dst histogram + zero cat denom + time_rel (blocks 0..5)
// (g_cnt is zeroed by a preceding memset node)
__global__ void k0_init(const float* __restrict__ nfeat, int NN,
                        const int* __restrict__ dst, int E,
                        const float* __restrict__ hour_emb,
                        const float* __restrict__ W,
                        const float* __restrict__ b) {
    int stride = gridDim.x * blockDim.x;
    int tid = blockIdx.x * blockDim.x + threadIdx.x;

    const float2* nf2 = (const float2*)nfeat;
    __half2* nh2 = (__half2*)g_nhalf;
    int n2 = NN * D / 2;
    for (int i = tid; i < n2; i += stride)
        nh2[i] = __float22half2_rn(nf2[i]);
    for (int e = tid; e < E; e += stride)
        atomicAdd(&g_cnt[dst[e]], 1);
    for (int i = tid; i < NC_NODES; i += stride)
        g_cdenom[i] = 0.f;

    if (blockIdx.x < HP) {
        __shared__ float mix[D];
        __shared__ float red[D];
        int h = blockIdx.x;
        int j = threadIdx.x;
        if (j < D) {
            int lh = (h - 1 + HP) % HP, nh = (h + 1) % HP;
            mix[j] = (hour_emb[lh * D + j] + hour_emb[h * D + j] + hour_emb[nh * D + j]) * (1.f / 3.f);
        }
        __syncthreads();
        float o = 0.f;
        if (j < D) {
            o = b[j];
            #pragma unroll
            for (int k = 0; k < D; k++) o = fmaf(W[j * D + k], mix[k], o);
            red[j] = o * o;
        }
        __syncthreads();
        #pragma unroll
        for (int s = 32; s > 0; s >>= 1) {
            if (j < s) red[j] += red[j + s];
            __syncthreads();
        }
        if (j < D) g_trel[h * D + j] = o / fmaxf(sqrtf(red[0]), 1e-12f);
    }
}

// K2: per-block scan (1024 elements/block, 256 threads x 4)
__global__ void k2_scan_blocks(int NN) {
    __shared__ int sh[256];
    int b = blockIdx.x, t = threadIdx.x;
    int base = b * SCAN_BLK + t * 4;
    int v0 = (base + 0 < NN) ? g_cnt[base + 0] : 0;
    int v1 = (base + 1 < NN) ? g_cnt[base + 1] : 0;
    int v2 = (base + 2 < NN) ? g_cnt[base + 2] : 0;
    int v3 = (base + 3 < NN) ? g_cnt[base + 3] : 0;
    int s = v0 + v1 + v2 + v3;
    sh[t] = s;
    __syncthreads();
    #pragma unroll
    for (int off = 1; off < 256; off <<= 1) {
        int x = (t >= off) ? sh[t - off] : 0;
        __syncthreads();
        sh[t] += x;
        __syncthreads();
    }
    if (t == 255) g_bsum[b] = sh[255];
    int run = sh[t] - s;
    if (base + 0 < NN) g_off[base + 0] = run; run += v0;
    if (base + 1 < NN) g_off[base + 1] = run; run += v1;
    if (base + 2 < NN) g_off[base + 2] = run; run += v2;
    if (base + 3 < NN) g_off[base + 3] = run;
}

// K3: parallel scan of the (<=128) block sums, one block of 128 threads
__global__ void k3_scan_sums(int nblk) {
    __shared__ int sh[128];
    int t = threadIdx.x;
    int v = (t < nblk) ? g_bsum[t] : 0;
    sh[t] = v;
    __syncthreads();
    #pragma unroll
    for (int off = 1; off < 128; off <<= 1) {
        int x = (t >= off) ? sh[t - off] : 0;
        __syncthreads();
        sh[t] += x;
        __syncthreads();
    }
    if (t < nblk) g_bpre[t] = sh[t] - v;
}

// K4: finalize row pointers + cursors
__global__ void k4_finalize(int NN, int E) {
    int i = blockIdx.x * blockDim.x + threadIdx.x;
    if (i < NN) {
        int v = g_off[i] + g_bpre[i >> 10];
        g_start[i] = v;
        g_cursor[i] = v;
    }
    if (i == 0) g_start[NN] = E;
}

// K5: scatter edges into CSR slots
__global__ void k5_scatter(const int* __restrict__ src,
                           const int* __restrict__ dst, int E) {
    int stride = gridDim.x * blockDim.x;
    for (int e = blockIdx.x * blockDim.x + threadIdx.x; e < E; e += stride) {
        int d = dst[e];
        int pos = atomicAdd(&g_cursor[d], 1);
        g_slot_src[pos] = src[e];
        g_eslot[e] = pos;
    }
}

// ---------------------------------------------------------------------------
// K6: pass-1 scores. warps < EC: cat edges (fp32). Others: 2 main edges/warp (fp16).
__global__ void k6_pass1(const float* __restrict__ cat_emb,
                         const float* __restrict__ rel_emb,
                         const float* __restrict__ norm_emb,
                         const int* __restrict__ src,
                         const int* __restrict__ dst,
                         const int* __restrict__ ftype,
                         const int* __restrict__ hourid,
                         const int* __restrict__ csrc,
                         const int* __restrict__ cdst,
                         int E, int EC, int n_warps) {
    int w = (blockIdx.x * blockDim.x + threadIdx.x) >> 5;
    int lane = threadIdx.x & 31;
    if (w >= n_warps) return;

    if (w < EC) {
        int e = w;
        int s = csrc[e], d = cdst[e];
        const float2* ce2 = (const float2*)cat_emb;
        const float2* re2 = (const float2*)rel_emb;
        float2 hc = ce2[s * 32 + lane];
        float2 tc = ce2[d * 32 + lane];
        float2 rc = re2[6 * 32 + lane];
        float dx = hc.x + rc.x - tc.x;
        float dy = hc.y + rc.y - tc.y;
        float ssq = warp_sum(fmaf(dx, dx, dy * dy));
        if (lane == 0) {
            float wgt = __expf(__expf(-ssq));
            g_cw[e] = wgt;
            atomicAdd(&g_cdenom[d], wgt);
        }
    } else {
        int p = w - EC;
        int half = lane >> 4;
        int l = lane & 15;
        int e = 2 * p + half;
        if (e >= E) return;
        int s = src[e], d = dst[e], f = ftype[e], h = hourid[e];

        const float2* nh2 = (const float2*)g_nhalf;   // 4 halfs per float2
        float2 ra = nh2[s * 16 + l];
        float2 rb = nh2[d * 16 + l];
        __half2* pa = (__half2*)&ra;
        __half2* pb = (__half2*)&rb;
        float2 a0 = __half22float2(pa[0]), a1 = __half22float2(pa[1]);
        float2 b0 = __half22float2(pb[0]), b1 = __half22float2(pb[1]);
        float ux = a0.x - b0.x, uy = a0.y - b0.y, uz = a1.x - b1.x, uw = a1.y - b1.y;

        const float4* nm4 = (const float4*)norm_emb;
        const float4* re4 = (const float4*)rel_emb;
        const float4* tr4 = (const float4*)g_trel;
        float4 n  = nm4[f * 16 + l];
        float4 tn = nm4[5 * 16 + l];

        float dot1 = half_sum(fmaf(ux, n.x,  fmaf(uy, n.y,  fmaf(uz, n.z,  uw * n.w))));
        float dot2 = half_sum(fmaf(ux, tn.x, fmaf(uy, tn.y, fmaf(uz, tn.z, uw * tn.w))));

        float4 r  = re4[f * 16 + l];
        float4 tr = tr4[h * 16 + l];

        float e1x = ux - dot1 * n.x + r.x;
        float e1y = uy - dot1 * n.y + r.y;
        float e1z = uz - dot1 * n.z + r.z;
        float e1w = uw - dot1 * n.w + r.w;
        float e2x = ux - dot2 * tn.x + tr.x;
        float e2y = uy - dot2 * tn.y + tr.y;
        float e2z = uz - dot2 * tn.z + tr.z;
        float e2w = uw - dot2 * tn.w + tr.w;

        float ssq = half_sum(
            fmaf(e1x, e1x, fmaf(e1y, e1y, fmaf(e1z, e1z, e1w * e1w))) +
            fmaf(e2x, e2x, fmaf(e2y, e2y, fmaf(e2z, e2z, e2w * e2w))));

        if (l == 0) {
            float wgt = __expf(__expf(-ssq));
            g_wslot[g_eslot[e]] = wgt;
        }
    }
}

// ---------------------------------------------------------------------------
// K7: warps < ECH: cat pass2 (REDG into zeroed cat_hid). Others: 2 nodes/warp gather.
__global__ void k7_aggregate(const float* __restrict__ cat_emb,
                             const int* __restrict__ csrc,
                             const int* __restrict__ cdst,
                             float* __restrict__ rst,
                             float* __restrict__ cat_hid,
                             int NN, int EC, int ECH, int n_warps) {
    int w = (blockIdx.x * blockDim.x + threadIdx.x) >> 5;
    int lane = threadIdx.x & 31;
    if (w >= n_warps) return;
    int half = lane >> 4;
    int l = lane & 15;

    if (w < ECH) {
        int e = 2 * w + half;
        if (e >= EC) return;
        int s = csrc[e], d = cdst[e];
        float coeff = g_cw[e] / g_cdenom[d];
        float4 v = ((const float4*)cat_emb)[s * 16 + l];
        red_add_v4(&cat_hid[d * D + l * 4],
                   v.x * coeff, v.y * coeff, v.z * coeff, v.w * coeff);
    } else {
        int node = 2 * (w - ECH) + half;
        if (node >= NN) return;
        int st = g_start[node], en = g_start[node + 1];
        float4 acc = make_float4(0.f, 0.f, 0.f, 0.f);
        if (en > st) {
            float denom = 0.f;
            for (int j = st + l; j < en; j += 16) denom += g_wslot[j];
            denom = half_sum(denom);
            float inv = 1.f / denom;
            const float2* nh2 = (const float2*)g_nhalf;
            for (int j = st; j < en; j++) {
                float cw = g_wslot[j] * inv;   // uniform across half-warp
                int s = g_slot_src[j];
                float2 rv = nh2[s * 16 + l];
                __half2* pv = (__half2*)&rv;
                float2 v0 = __half22float2(pv[0]), v1 = __half22float2(pv[1]);
                acc.x = fmaf(cw, v0.x, acc.x);
                acc.y = fmaf(cw, v0.y, acc.y);
                acc.z = fmaf(cw, v1.x, acc.z);
                acc.w = fmaf(cw, v1.y, acc.w);
            }
        }
        ((float4*)rst)[node * 16 + l] = acc;
    }
}

// ---------------------------------------------------------------------------
extern "C" void kernel_launch(void* const* d_in, const int* in_sizes, int n_in,
                              void* d_out, int out_size) {
    const float* nfeat      = (const float*)d_in[0];
    const float* cat_emb    = (const float*)d_in[1];
    const float* rel_emb    = (const float*)d_in[2];
    const float* norm_emb   = (const float*)d_in[3];
    const float* hour_emb   = (const float*)d_in[4];
    const float* time_rel_w = (const float*)d_in[5];
    const float* time_rel_b = (const float*)d_in[6];
    const int*   src        = (const int*)d_in[7];
    const int*   dst        = (const int*)d_in[8];
    const int*   ftype      = (const int*)d_in[9];
    const int*   hourid     = (const int*)d_in[10];
    const int*   cat_src    = (const int*)d_in[11];
    const int*   cat_dst    = (const int*)d_in[12];

    const int NN = in_sizes[0] / D;
    const int E  = in_sizes[7];
    const int EC = in_sizes[11];

    float* out     = (float*)d_out;
    float* rst     = out;
    float* cat_hid = out + NN * D;

    // Zero the edge counters (memset node) and the REDG-target cat_hid region
    void* cnt_addr = nullptr;
    cudaGetSymbolAddress(&cnt_addr, g_cnt);
    cudaMemsetAsync(cnt_addr, 0, (size_t)NN * sizeof(int), 0);
    cudaMemsetAsync(cat_hid, 0, (size_t)NC_NODES * D * sizeof(float), 0);

    // K0: convert + count + time_rel
    k0_init<<<2048, 256>>>(nfeat, NN, dst, E, hour_emb, time_rel_w, time_rel_b);

    // CSR build
    int nblk = (NN + SCAN_BLK - 1) / SCAN_BLK;
    k2_scan_blocks<<<nblk, 256>>>(NN);
    k3_scan_sums<<<1, 128>>>(nblk);
    k4_finalize<<<(NN + 255) / 256, 256>>>(NN, E);
    k5_scatter<<<1024, 256>>>(src, dst, E);

    // Pass 1
    {
        int n_warps = EC + (E + 1) / 2;
        int blocks = (n_warps * 32 + 255) / 256;
        k6_pass1<<<blocks, 256>>>(cat_emb, rel_emb, norm_emb,
                                  src, dst, ftype, hourid, cat_src, cat_dst,
                                  E, EC, n_warps);
    }

    // Pass 2
    {
        int ECH = (EC + 1) / 2;
        int n_warps = ECH + (NN + 1) / 2;
        int blocks = (n_warps * 32 + 255) / 256;
        k7_aggregate<<<blocks, 256>>>(cat_emb, cat_src, cat_dst,
                                      rst, cat_hid, NN, EC, ECH, n_warps);
    }
}

// round 6
// speedup vs baseline: 1.1526x; 1.0553x over previous
#include <cuda_runtime.h>
#include <cuda_fp16.h>

#define D        64
#define N_MAX    100000
#define E_MAX    800000
#define NC_NODES 500
#define EC_MAX   20000
#define HP       6
#define SCAN_BLK 1024
#define NBLK_MAX ((N_MAX + SCAN_BLK - 1) / SCAN_BLK)

// Static scratch
__device__ __half g_nhalf[N_MAX * D];   // fp16 copy of nfeat
__device__ float  g_wslot[E_MAX];       // softmax weight per CSR slot
__device__ float  g_cw[EC_MAX];
__device__ float  g_cdenom[NC_NODES];
__device__ float  g_trel[HP * D];
__device__ int    g_cnt[N_MAX];         // ==0 at entry (static init; k4 resets each call)
__device__ int    g_off[N_MAX];
__device__ int    g_bsum[NBLK_MAX];
__device__ int    g_bpre[NBLK_MAX];
__device__ int    g_start[N_MAX + 1];
__device__ int    g_cursor[N_MAX];
__device__ int    g_slot_src[E_MAX];

// ---------------------------------------------------------------------------
__device__ __forceinline__ float sum8(float v) {
    #pragma unroll
    for (int o = 4; o > 0; o >>= 1) v += __shfl_xor_sync(0xffffffffu, v, o);
    return v;
}
__device__ __forceinline__ float half_sum(float v) {
    #pragma unroll
    for (int o = 8; o > 0; o >>= 1) v += __shfl_xor_sync(0xffffffffu, v, o);
    return v;
}
__device__ __forceinline__ void red_add_v4(float* p, float x, float y, float z, float w) {
    asm volatile("red.global.add.v4.f32 [%0], {%1,%2,%3,%4};"
                 :: "l"(p), "f"(x), "f"(y), "f"(z), "f"(w) : "memory");
}
// unpack a float4 holding 8 halfs into 8 floats
__device__ __forceinline__ void unpack8(float4 v, float* o) {
    const __half2* p = (const __half2*)&v;
    float2 f0 = __half22float2(p[0]);
    float2 f1 = __half22float2(p[1]);
    float2 f2 = __half22float2(p[2]);
    float2 f3 = __half22float2(p[3]);
    o[0] = f0.x; o[1] = f0.y; o[2] = f1.x; o[3] = f1.y;
    o[4] = f2.x; o[5] = f2.y; o[6] = f3.x; o[7] = f3.y;
}

// ---------------------------------------------------------------------------
// K0: fp16 convert + dst histogram + zero cat_hid/cdenom + time_rel (blocks 0..5)
__global__ void k0_init(const float* __restrict__ nfeat, int NN,
                        const int* __restrict__ dst, int E,
                        float* __restrict__ cat_hid,
                        const float* __restrict__ hour_emb,
                        const float* __restrict__ W,
                        const float* __restrict__ b) {
    int stride = gridDim.x * blockDim.x;
    int tid = blockIdx.x * blockDim.x + threadIdx.x;

    const float2* nf2 = (const float2*)nfeat;
    __half2* nh2 = (__half2*)g_nhalf;
    int n2 = NN * D / 2;
    for (int i = tid; i < n2; i += stride)
        nh2[i] = __float22half2_rn(nf2[i]);
    for (int e = tid; e < E; e += stride)
        atomicAdd(&g_cnt[dst[e]], 1);
    for (int i = tid; i < NC_NODES * D; i += stride)
        cat_hid[i] = 0.f;
    for (int i = tid; i < NC_NODES; i += stride)
        g_cdenom[i] = 0.f;

    if (blockIdx.x < HP) {
        __shared__ float mix[D];
        __shared__ float red[D];
        int h = blockIdx.x;
        int j = threadIdx.x;
        if (j < D) {
            int lh = (h - 1 + HP) % HP, nh = (h + 1) % HP;
            mix[j] = (hour_emb[lh * D + j] + hour_emb[h * D + j] + hour_emb[nh * D + j]) * (1.f / 3.f);
        }
        __syncthreads();
        float o = 0.f;
        if (j < D) {
            o = b[j];
            #pragma unroll
            for (int k = 0; k < D; k++) o = fmaf(W[j * D + k], mix[k], o);
            red[j] = o * o;
        }
        __syncthreads();
        #pragma unroll
        for (int s = 32; s > 0; s >>= 1) {
            if (j < s) red[j] += red[j + s];
            __syncthreads();
        }
        if (j < D) g_trel[h * D + j] = o / fmaxf(sqrtf(red[0]), 1e-12f);
    }
}

// K2: per-block scan (1024 elements/block, 256 threads x 4)
__global__ void k2_scan_blocks(int NN) {
    __shared__ int sh[256];
    int b = blockIdx.x, t = threadIdx.x;
    int base = b * SCAN_BLK + t * 4;
    int v0 = (base + 0 < NN) ? g_cnt[base + 0] : 0;
    int v1 = (base + 1 < NN) ? g_cnt[base + 1] : 0;
    int v2 = (base + 2 < NN) ? g_cnt[base + 2] : 0;
    int v3 = (base + 3 < NN) ? g_cnt[base + 3] : 0;
    int s = v0 + v1 + v2 + v3;
    sh[t] = s;
    __syncthreads();
    #pragma unroll
    for (int off = 1; off < 256; off <<= 1) {
        int x = (t >= off) ? sh[t - off] : 0;
        __syncthreads();
        sh[t] += x;
        __syncthreads();
    }
    if (t == 255) g_bsum[b] = sh[255];
    int run = sh[t] - s;
    if (base + 0 < NN) g_off[base + 0] = run; run += v0;
    if (base + 1 < NN) g_off[base + 1] = run; run += v1;
    if (base + 2 < NN) g_off[base + 2] = run; run += v2;
    if (base + 3 < NN) g_off[base + 3] = run;
}

// K3: parallel scan of the (<=128) block sums
__global__ void k3_scan_sums(int nblk) {
    __shared__ int sh[128];
    int t = threadIdx.x;
    int v = (t < nblk) ? g_bsum[t] : 0;
    sh[t] = v;
    __syncthreads();
    #pragma unroll
    for (int off = 1; off < 128; off <<= 1) {
        int x = (t >= off) ? sh[t - off] : 0;
        __syncthreads();
        sh[t] += x;
        __syncthreads();
    }
    if (t < nblk) g_bpre[t] = sh[t] - v;
}

// K4: finalize row pointers + cursors; reset g_cnt for the next call
__global__ void k4_finalize(int NN, int E) {
    int i = blockIdx.x * blockDim.x + threadIdx.x;
    if (i < NN) {
        int v = g_off[i] + g_bpre[i >> 10];
        g_start[i] = v;
        g_cursor[i] = v;
        g_cnt[i] = 0;
    }
    if (i == 0) g_start[NN] = E;
}

// ---------------------------------------------------------------------------
// K6: pass-1 scores, 8 lanes per edge, 4 edges per warp, fused CSR scatter.
//   warp w < warps_cat : 4 category edges
//   warp w >= warps_cat: 4 main edges
__global__ void __launch_bounds__(256) k6_pass1(
        const float* __restrict__ cat_emb,
        const float* __restrict__ rel_emb,
        const float* __restrict__ norm_emb,
        const int* __restrict__ src,
        const int* __restrict__ dst,
        const int* __restrict__ ftype,
        const int* __restrict__ hourid,
        const int* __restrict__ csrc,
        const int* __restrict__ cdst,
        int E, int EC, int warps_cat, int n_warps) {
    int w = (blockIdx.x * blockDim.x + threadIdx.x) >> 5;
    int lane = threadIdx.x & 31;
    if (w >= n_warps) return;
    int grp = lane >> 3;       // 0..3
    int l   = lane & 7;        // 0..7

    if (w < warps_cat) {
        int e = 4 * w + grp;
        bool valid = (e < EC);
        int ec = valid ? e : EC - 1;
        int s = csrc[ec], d = cdst[ec];
        const float4* ce4 = (const float4*)cat_emb;
        const float4* re4 = (const float4*)rel_emb;
        float ssq = 0.f;
        #pragma unroll
        for (int q = 0; q < 2; q++) {
            float4 hc = ce4[s * 16 + 2 * l + q];
            float4 tc = ce4[d * 16 + 2 * l + q];
            float4 rc = re4[6 * 16 + 2 * l + q];
            float dx = hc.x + rc.x - tc.x;
            float dy = hc.y + rc.y - tc.y;
            float dz = hc.z + rc.z - tc.z;
            float dw = hc.w + rc.w - tc.w;
            ssq += fmaf(dx, dx, fmaf(dy, dy, fmaf(dz, dz, dw * dw)));
        }
        ssq = sum8(ssq);
        if (l == 0 && valid) {
            float wgt = __expf(__expf(-ssq));
            g_cw[e] = wgt;
            atomicAdd(&g_cdenom[d], wgt);
        }
    } else {
        int e = 4 * (w - warps_cat) + grp;
        bool valid = (e < E);
        int ec = valid ? e : E - 1;
        int s = src[ec], d = dst[ec], f = ftype[ec], h = hourid[ec];

        const float4* nh4 = (const float4*)g_nhalf;   // 8 halfs per float4, 8 float4/row
        float a[8], bb[8], u[8];
        unpack8(nh4[s * 8 + l], a);
        unpack8(nh4[d * 8 + l], bb);
        #pragma unroll
        for (int i = 0; i < 8; i++) u[i] = a[i] - bb[i];

        const float4* nm4 = (const float4*)norm_emb;  // 16 float4 per row
        const float4* re4 = (const float4*)rel_emb;
        const float4* tr4 = (const float4*)g_trel;

        float4 n0  = nm4[f * 16 + 2 * l],  n1  = nm4[f * 16 + 2 * l + 1];
        float4 tn0 = nm4[5 * 16 + 2 * l],  tn1 = nm4[5 * 16 + 2 * l + 1];
        float n[8]  = {n0.x, n0.y, n0.z, n0.w, n1.x, n1.y, n1.z, n1.w};
        float tn[8] = {tn0.x, tn0.y, tn0.z, tn0.w, tn1.x, tn1.y, tn1.z, tn1.w};

        float p1 = 0.f, p2 = 0.f;
        #pragma unroll
        for (int i = 0; i < 8; i++) {
            p1 = fmaf(u[i], n[i], p1);
            p2 = fmaf(u[i], tn[i], p2);
        }
        float dot1 = sum8(p1);
        float dot2 = sum8(p2);

        float4 r0  = re4[f * 16 + 2 * l],  r1  = re4[f * 16 + 2 * l + 1];
        float4 t0  = tr4[h * 16 + 2 * l],  t1  = tr4[h * 16 + 2 * l + 1];
        float r[8]  = {r0.x, r0.y, r0.z, r0.w, r1.x, r1.y, r1.z, r1.w};
        float tr[8] = {t0.x, t0.y, t0.z, t0.w, t1.x, t1.y, t1.z, t1.w};

        float ssq = 0.f;
        #pragma unroll
        for (int i = 0; i < 8; i++) {
            float d1 = u[i] - dot1 * n[i] + r[i];
            float d2 = u[i] - dot2 * tn[i] + tr[i];
            ssq = fmaf(d1, d1, fmaf(d2, d2, ssq));
        }
        ssq = sum8(ssq);

        if (l == 0 && valid) {
            float wgt = __expf(__expf(-ssq));
            int pos = atomicAdd(&g_cursor[d], 1);
            g_slot_src[pos] = s;
            g_wslot[pos] = wgt;
        }
    }
}

// ---------------------------------------------------------------------------
// K7: warps < ECH: cat pass2 (REDG into zeroed cat_hid). Others: 2 nodes/warp gather.
__global__ void k7_aggregate(const float* __restrict__ cat_emb,
                             const int* __restrict__ csrc,
                             const int* __restrict__ cdst,
                             float* __restrict__ rst,
                             float* __restrict__ cat_hid,
                             int NN, int EC, int ECH, int n_warps) {
    int w = (blockIdx.x * blockDim.x + threadIdx.x) >> 5;
    int lane = threadIdx.x & 31;
    if (w >= n_warps) return;
    int half = lane >> 4;
    int l = lane & 15;

    if (w < ECH) {
        int e = 2 * w + half;
        if (e >= EC) return;
        int s = csrc[e], d = cdst[e];
        float coeff = g_cw[e] / g_cdenom[d];
        float4 v = ((const float4*)cat_emb)[s * 16 + l];
        red_add_v4(&cat_hid[d * D + l * 4],
                   v.x * coeff, v.y * coeff, v.z * coeff, v.w * coeff);
    } else {
        int node = 2 * (w - ECH) + half;
        if (node >= NN) return;
        int st = g_start[node], en = g_start[node + 1];
        float4 acc = make_float4(0.f, 0.f, 0.f, 0.f);
        if (en > st) {
            float denom = 0.f;
            for (int j = st + l; j < en; j += 16) denom += g_wslot[j];
            denom = half_sum(denom);
            float inv = 1.f / denom;
            const float2* nh2 = (const float2*)g_nhalf;
            for (int j = st; j < en; j++) {
                float cw = g_wslot[j] * inv;
                int s = g_slot_src[j];
                float2 rv = nh2[s * 16 + l];
                __half2* pv = (__half2*)&rv;
                float2 v0 = __half22float2(pv[0]), v1 = __half22float2(pv[1]);
                acc.x = fmaf(cw, v0.x, acc.x);
                acc.y = fmaf(cw, v0.y, acc.y);
                acc.z = fmaf(cw, v1.x, acc.z);
                acc.w = fmaf(cw, v1.y, acc.w);
            }
        }
        ((float4*)rst)[node * 16 + l] = acc;
    }
}

// ---------------------------------------------------------------------------
extern "C" void kernel_launch(void* const* d_in, const int* in_sizes, int n_in,
                              void* d_out, int out_size) {
    const float* nfeat      = (const float*)d_in[0];
    const float* cat_emb    = (const float*)d_in[1];
    const float* rel_emb    = (const float*)d_in[2];
    const float* norm_emb   = (const float*)d_in[3];
    const float* hour_emb   = (const float*)d_in[4];
    const float* time_rel_w = (const float*)d_in[5];
    const float* time_rel_b = (const float*)d_in[6];
    const int*   src        = (const int*)d_in[7];
    const int*   dst        = (const int*)d_in[8];
    const int*   ftype      = (const int*)d_in[9];
    const int*   hourid     = (const int*)d_in[10];
    const int*   cat_src    = (const int*)d_in[11];
    const int*   cat_dst    = (const int*)d_in[12];

    const int NN = in_sizes[0] / D;
    const int E  = in_sizes[7];
    const int EC = in_sizes[11];

    float* out     = (float*)d_out;
    float* rst     = out;
    float* cat_hid = out + NN * D;

    // K0: convert + histogram + zeros + time_rel
    k0_init<<<2048, 256>>>(nfeat, NN, dst, E, cat_hid, hour_emb, time_rel_w, time_rel_b);

    // CSR build (scan only; scatter fused into pass1)
    int nblk = (NN + SCAN_BLK - 1) / SCAN_BLK;
    k2_scan_blocks<<<nblk, 256>>>(NN);
    k3_scan_sums<<<1, 128>>>(nblk);
    k4_finalize<<<(NN + 511) / 512, 512>>>(NN, E);

    // Pass 1 (scores + fused scatter)
    {
        int warps_cat = (EC + 3) / 4;
        int n_warps = warps_cat + (E + 3) / 4;
        int blocks = (n_warps * 32 + 255) / 256;
        k6_pass1<<<blocks, 256>>>(cat_emb, rel_emb, norm_emb,
                                  src, dst, ftype, hourid, cat_src, cat_dst,
                                  E, EC, warps_cat, n_warps);
    }

    // Pass 2 (aggregate)
    {
        int ECH = (EC + 1) / 2;
        int n_warps = ECH + (NN + 1) / 2;
        int blocks = (n_warps * 32 + 255) / 256;
        k7_aggregate<<<blocks, 256>>>(cat_emb, cat_src, cat_dst,
                                      rst, cat_hid, NN, EC, ECH, n_warps);
    }
}